// round 15
// baseline (speedup 1.0000x reference)
#include <cuda_runtime.h>
#include <cuda_fp16.h>

// Problem constants (fixed by the dataset)
#define NN 50000      // nodes
#define HH 5000       // hyperedges
#define EE 400000     // incidence entries
#define RR (NN*2)     // (n,b) rows, r = 2n+b

#define DEG_BLOCKS 1563   // ceil(EE/256)
#define PREP_BLOCKS 12500 // RR/8 rows, 8 warps per block
#define SCHUNK 49         // scan chunk: 1024*49 >= NN

// ---------------------------------------------------------------------------
// Scratch (__device__ globals; zero-initialized at load; self-resetting)
// ---------------------------------------------------------------------------
__device__ __align__(16) __half g_xh[RR * 64];   // fp16 x, row r=2n+b (12.8 MB)
__device__ __align__(16) float  g_d1[RR];        // x . (W@att1)
__device__ __align__(16) float  g_d2[RR];        // x . (W@att2)
__device__ __align__(16) float  g_w[128];        // w1[64], w2[64]
__device__ volatile int g_wflag;                 // w ready flag (never reset; benign)
__device__ int   g_Dn[NN];                       // node degree (reset in pass2)
__device__ int   g_nstart[NN];                   // node segment starts
__device__ int   g_cursor[NN];                   // scatter cursors (reset by last-arriver)
__device__ int   g_done[NN];                     // completion counts (reset by last-arriver)
__device__ int   g_hstart[HH + 1];               // hyperedge segment starts (+sentinel)
__device__ __align__(16) float  g_aedge[HH * 2]; // per-hyperedge attention scalar
__device__ int   g_sh[EE];                       // hyperedge id per node-sorted slot
__device__ __align__(16) float  g_ni[NN * 8];    // per-node {d1_0,d1_1,mx0,mx1,inv0,inv1,deg,-}
__device__ __align__(16) __half g_mh[HH * 128];  // projected messages m (fp16)

// ---------------------------------------------------------------------------
// K1: block 0        -> g_w = {W@att1, W@att2}, then release flag
//     blocks 1..1563 -> node degrees (atomic) + hstart boundary fill
//     blocks 1564..  -> per-row d1,d2 + fp16 quantize of x (spin on flag)
// ---------------------------------------------------------------------------
__global__ void k1_prep(const float* __restrict__ x,
                        const float* __restrict__ W,
                        const float* __restrict__ att,
                        const int* __restrict__ node_idx,
                        const int* __restrict__ hedge_idx) {
    int b = blockIdx.x, t = threadIdx.x;
    if (b == 0) {
        if (t < 128) {
            int d = t & 63;
            const float* a = att + (t >> 6) * 64;
            float s = 0.f;
#pragma unroll
            for (int c = 0; c < 64; c++) s += W[d * 64 + c] * a[c];  // row d of W
            g_w[t] = s;
        }
        __syncthreads();
        __threadfence();
        if (t == 0) g_wflag = 1;
    } else if (b <= DEG_BLOCKS) {
        int e = (b - 1) * 256 + t;
        if (e >= EE) return;
        atomicAdd(&g_Dn[node_idx[e]], 1);
        int h  = hedge_idx[e];
        int hp = (e == 0) ? -1 : hedge_idx[e - 1];
        if (h != hp)
            for (int g = hp + 1; g <= h; g++) g_hstart[g] = e;
        if (e == EE - 1)
            for (int g = h + 1; g <= HH; g++) g_hstart[g] = EE;
    } else {
        if (t == 0) { while (g_wflag == 0) __nanosleep(64); }
        __syncthreads();            // block-wide fence: g_w visible after flag
        int warp = t >> 5, lane = t & 31;
        int r = (b - (DEG_BLOCKS + 1)) * 8 + warp;   // < RR always
        int n = r >> 1, bb = r & 1;
        float2 xv = *(const float2*)(x + (size_t)bb * NN * 64 + (size_t)n * 64 + lane * 2);
        float2 w1 = *(const float2*)(g_w + 2 * lane);
        float2 w2 = *(const float2*)(g_w + 64 + 2 * lane);
        float p1 = xv.x * w1.x + xv.y * w1.y;
        float p2 = xv.x * w2.x + xv.y * w2.y;
#pragma unroll
        for (int off = 16; off >= 1; off >>= 1) {
            p1 += __shfl_xor_sync(0xffffffffu, p1, off);
            p2 += __shfl_xor_sync(0xffffffffu, p2, off);
        }
        if (lane == 0) { g_d1[r] = p1; g_d2[r] = p2; }
        *(__half2*)(g_xh + (size_t)r * 64 + lane * 2) = __floats2half2_rn(xv.x, xv.y);
    }
}

// ---------------------------------------------------------------------------
// K2: block 0 (1024 thr) = exclusive scan of Dn -> nstart (49 elems/thread)
//     blocks 1..625      = 8 hyperedges each: aedge[h][b] = sum d2[2n+b]
// ---------------------------------------------------------------------------
__global__ void k2_scan_aedge(const int* __restrict__ node_idx) {
    int t = threadIdx.x;
    if (blockIdx.x == 0) {
        int begin = t * SCHUNK;
        int end   = min(begin + SCHUNK, NN);
        int s = 0;
        for (int i = begin; i < end; i++) s += g_Dn[i];
        int lane = t & 31, wid = t >> 5;
        int inc = s;
#pragma unroll
        for (int off = 1; off < 32; off <<= 1) {
            int y = __shfl_up_sync(0xffffffffu, inc, off);
            if (lane >= off) inc += y;
        }
        __shared__ int ws[32];
        if (lane == 31) ws[wid] = inc;
        __syncthreads();
        if (wid == 0) {
            int v = ws[lane];
#pragma unroll
            for (int off = 1; off < 32; off <<= 1) {
                int y = __shfl_up_sync(0xffffffffu, v, off);
                if (lane >= off) v += y;
            }
            ws[lane] = v;
        }
        __syncthreads();
        int run = inc - s + ((wid > 0) ? ws[wid - 1] : 0);
        for (int i = begin; i < end; i++) { g_nstart[i] = run; run += g_Dn[i]; }
    } else {
        int g  = t >> 7;            // group 0..7, 128 threads each
        int gt = t & 127;
        int h  = (blockIdx.x - 1) * 8 + g;    // < 5000 exactly (625*8)
        int s  = g_hstart[h];
        int cnt = g_hstart[h + 1] - s;
        float s0 = 0.f, s1 = 0.f;
        for (int i = gt; i < cnt; i += 128) {
            int n = node_idx[s + i];
            float2 d = *(const float2*)(g_d2 + 2 * n);
            s0 += d.x; s1 += d.y;
        }
#pragma unroll
        for (int off = 16; off >= 1; off >>= 1) {
            s0 += __shfl_xor_sync(0xffffffffu, s0, off);
            s1 += __shfl_xor_sync(0xffffffffu, s1, off);
        }
        __shared__ float r0[8][4], r1[8][4];
        int lane = gt & 31, wig = gt >> 5;
        if (lane == 0) { r0[g][wig] = s0; r1[g][wig] = s1; }
        __syncthreads();
        if (gt == 0) {
            g_aedge[2 * h]     = r0[g][0] + r0[g][1] + r0[g][2] + r0[g][3];
            g_aedge[2 * h + 1] = r1[g][0] + r1[g][1] + r1[g][2] + r1[g][3];
        }
    }
}

// ---------------------------------------------------------------------------
// K3: counting-sort scatter + last-arriver computes per-node softmax stats.
//     Release/acquire via the done-counter atomic itself (no full membar per
//     thread); winner self-resets cursor/done for the next graph replay.
// ---------------------------------------------------------------------------
__global__ void k3_scatter_stats(const int* __restrict__ node_idx,
                                 const int* __restrict__ hedge_idx) {
    int e = blockIdx.x * 256 + threadIdx.x;
    if (e >= EE) return;
    int n = node_idx[e], h = hedge_idx[e];
    int pos = g_nstart[n] + atomicAdd(&g_cursor[n], 1);
    g_sh[pos] = h;
    int deg = g_Dn[n];
    int old;
    // release: orders the g_sh store above; acquire: winner sees all g_sh.
    asm volatile("atom.acq_rel.gpu.global.add.s32 %0, [%1], %2;"
                 : "=r"(old) : "l"(g_done + n), "r"(1) : "memory");
    if (old == deg - 1) {
        g_cursor[n] = 0; g_done[n] = 0;       // self-reset (no more writers for n)
        int start = g_nstart[n];
        float d10 = g_d1[2 * n], d11 = g_d1[2 * n + 1];
        float m0 = -1e30f, m1 = -1e30f, s0 = 0.f, s1 = 0.f;
        for (int j = 0; j < deg; j++) {
            int hh = g_sh[start + j];
            float2 ae = *(const float2*)(g_aedge + 2 * hh);
            float v0 = d10 + ae.x; v0 = (v0 >= 0.f) ? v0 : 0.2f * v0;
            float v1 = d11 + ae.y; v1 = (v1 >= 0.f) ? v1 : 0.2f * v1;
            if (v0 > m0) { s0 = s0 * __expf(m0 - v0) + 1.f; m0 = v0; }
            else         { s0 += __expf(v0 - m0); }
            if (v1 > m1) { s1 = s1 * __expf(m1 - v1) + 1.f; m1 = v1; }
            else         { s1 += __expf(v1 - m1); }
        }
        *(float4*)(g_ni + n * 8)     = make_float4(d10, d11, m0, m1);
        *(float4*)(g_ni + n * 8 + 4) = make_float4(1.f / s0, 1.f / s1, (float)deg, 0.f);
    }
}

// ---------------------------------------------------------------------------
// K4: pass1 + projection fused (block per hyperedge, 128 threads):
//     Each lane loads uint4 (8 halfs); a half-warp covers a full 256B node
//     row, so one warp handles TWO incidences per LDG.128. 8 incid/iteration.
//     agg = (1/cnt) * sum alpha_e * x_fp16[n_e];  m = agg @ W -> g_mh (fp16)
// ---------------------------------------------------------------------------
__global__ void k4_pass1m(const int* __restrict__ node_idx,
                          const float* __restrict__ W) {
    int h = blockIdx.x, t = threadIdx.x;
    int s = g_hstart[h];
    int cnt = g_hstart[h + 1] - s;
    if (cnt == 0) { g_mh[h * 128 + t] = __float2half(0.f); return; }
    float2 ae = *(const float2*)(g_aedge + 2 * h);

    int w    = t >> 5;            // warp 0..3
    int lane = t & 31;
    int half = lane >> 4;         // which incidence of the warp's pair
    int hl   = lane & 15;         // owns halfs [hl*8, hl*8+8) of the row
    int bsel = hl >> 3;           // batch of those 8 halfs

    __shared__ int   sn[128];
    __shared__ float sa[2][128];
    __shared__ __align__(16) float red[4][32][8];
    __shared__ float sA[128];

    float4 alo = make_float4(0.f, 0.f, 0.f, 0.f);
    float4 ahi = make_float4(0.f, 0.f, 0.f, 0.f);
    for (int base = 0; base < cnt; base += 128) {
        int mlen = min(128, cnt - base);
        __syncthreads();
        if (t < mlen) {
            int n = node_idx[s + base + t];
            float4 na = *(const float4*)(g_ni + n * 8);
            float4 nb = *(const float4*)(g_ni + n * 8 + 4);
            float v0 = na.x + ae.x; v0 = (v0 >= 0.f) ? v0 : 0.2f * v0;
            float v1 = na.y + ae.y; v1 = (v1 >= 0.f) ? v1 : 0.2f * v1;
            sn[t]    = n;
            sa[0][t] = __expf(v0 - na.z) * nb.x;
            sa[1][t] = __expf(v1 - na.w) * nb.y;
        }
        __syncthreads();
        for (int i = w * 2 + half; i < mlen; i += 8) {
            int n = sn[i];
            float a = sa[bsel][i];
            uint4 raw = *(const uint4*)(g_xh + (size_t)n * 128 + hl * 8);
            float2 u0 = __half22float2(*(const __half2*)&raw.x);
            float2 u1 = __half22float2(*(const __half2*)&raw.y);
            float2 u2 = __half22float2(*(const __half2*)&raw.z);
            float2 u3 = __half22float2(*(const __half2*)&raw.w);
            alo.x += a * u0.x; alo.y += a * u0.y;
            alo.z += a * u1.x; alo.w += a * u1.y;
            ahi.x += a * u2.x; ahi.y += a * u2.y;
            ahi.z += a * u3.x; ahi.w += a * u3.y;
        }
    }
    *(float4*)&red[w][lane][0] = alo;
    *(float4*)&red[w][lane][4] = ahi;
    __syncthreads();
    // channel t: sum 8 partials (4 warps x 2 halves) for chunk t>>3, off t&7
    {
        int chunk = t >> 3, off = t & 7;
        float ssum = 0.f;
#pragma unroll
        for (int ww = 0; ww < 4; ww++)
            ssum += red[ww][chunk][off] + red[ww][16 + chunk][off];
        sA[t] = ssum * (1.0f / (float)cnt);
    }
    __syncthreads();
    // projection: thread t = (b, d); m[b][d] = sum_c agg[b][c] * W[c][d]
    int d = t & 63;
    const float* arow = sA + (t >> 6) * 64;
    float m = 0.f;
#pragma unroll 8
    for (int c = 0; c < 64; c++)
        m += arow[c] * __ldg(W + c * 64 + d);
    g_mh[h * 128 + t] = __float2half(m);
}

// ---------------------------------------------------------------------------
// K5: pass2: out[b][n][c] = deg * sum alpha_e * m_fp16[h_e] (warp per node)
//     Half-warp per incidence, uint4 loads (one LDG.128 covers 2 incidences
//     per warp); cross-half shfl_xor(16) reduction; resets g_Dn.
// ---------------------------------------------------------------------------
__global__ void k5_pass2(float* __restrict__ out) {
    int wip  = threadIdx.x >> 5;                       // warp in block (0..7)
    int gw   = (blockIdx.x * blockDim.x + threadIdx.x) >> 5;
    int lane = threadIdx.x & 31;
    __shared__ int    sh_h[8][32];
    __shared__ float2 sh_a[8][32];
    if (gw >= NN) return;
    int n = gw, deg = g_Dn[n];
    int start = g_nstart[n];
    float4 na = *(const float4*)(g_ni + n * 8);
    float4 nb = *(const float4*)(g_ni + n * 8 + 4);
    int half = lane >> 4;         // which incidence of the pair
    int hl   = lane & 15;         // owns halfs [hl*8, hl*8+8)
    int bsel = hl >> 3;           // batch of those 8 halfs
    float4 alo = make_float4(0.f, 0.f, 0.f, 0.f);
    float4 ahi = make_float4(0.f, 0.f, 0.f, 0.f);

    for (int base = 0; base < deg; base += 32) {
        int cnt = min(32, deg - base);
        if (lane < cnt) {
            int h = g_sh[start + base + lane];
            float2 aev = *(const float2*)(g_aedge + 2 * h);
            float v0 = na.x + aev.x; v0 = (v0 >= 0.f) ? v0 : 0.2f * v0;
            float v1 = na.y + aev.y; v1 = (v1 >= 0.f) ? v1 : 0.2f * v1;
            sh_h[wip][lane] = h;
            sh_a[wip][lane] = make_float2(__expf(v0 - na.z) * nb.x,
                                          __expf(v1 - na.w) * nb.y);
        }
        __syncwarp();
        for (int i = half; i < cnt; i += 2) {
            int    hh = sh_h[wip][i];
            float2 av = sh_a[wip][i];
            float  aa = bsel ? av.y : av.x;
            uint4 raw = *(const uint4*)(g_mh + (size_t)hh * 128 + hl * 8);
            float2 u0 = __half22float2(*(const __half2*)&raw.x);
            float2 u1 = __half22float2(*(const __half2*)&raw.y);
            float2 u2 = __half22float2(*(const __half2*)&raw.z);
            float2 u3 = __half22float2(*(const __half2*)&raw.w);
            alo.x += aa * u0.x; alo.y += aa * u0.y;
            alo.z += aa * u1.x; alo.w += aa * u1.y;
            ahi.x += aa * u2.x; ahi.y += aa * u2.y;
            ahi.z += aa * u3.x; ahi.w += aa * u3.y;
        }
        __syncwarp();
    }
    // combine the two incidence-halves: lanes l and l+16 hold same channels
    alo.x += __shfl_xor_sync(0xffffffffu, alo.x, 16);
    alo.y += __shfl_xor_sync(0xffffffffu, alo.y, 16);
    alo.z += __shfl_xor_sync(0xffffffffu, alo.z, 16);
    alo.w += __shfl_xor_sync(0xffffffffu, alo.w, 16);
    ahi.x += __shfl_xor_sync(0xffffffffu, ahi.x, 16);
    ahi.y += __shfl_xor_sync(0xffffffffu, ahi.y, 16);
    ahi.z += __shfl_xor_sync(0xffffffffu, ahi.z, 16);
    ahi.w += __shfl_xor_sync(0xffffffffu, ahi.w, 16);
    if (lane == 0) g_Dn[n] = 0;       // self-reset for next replay
    if (half == 0) {
        float dn = (float)deg;
        int b  = hl >> 3;
        int c0 = (hl & 7) * 8;
        float* o = out + (size_t)b * NN * 64 + (size_t)n * 64 + c0;
        *(float4*)o       = make_float4(dn * alo.x, dn * alo.y, dn * alo.z, dn * alo.w);
        *(float4*)(o + 4) = make_float4(dn * ahi.x, dn * ahi.y, dn * ahi.z, dn * ahi.w);
    }
}

// ---------------------------------------------------------------------------
// Launch: 5 kernels
// ---------------------------------------------------------------------------
extern "C" void kernel_launch(void* const* d_in, const int* in_sizes, int n_in,
                              void* d_out, int out_size) {
    const float* x         = (const float*)d_in[0];   // [B,N,C]
    const float* weight    = (const float*)d_in[1];   // [C,C]
    const float* att       = (const float*)d_in[2];   // [2C]
    const int*   node_idx  = (const int*)d_in[3];     // [E]
    const int*   hedge_idx = (const int*)d_in[4];     // [E] sorted
    float*       out       = (float*)d_out;           // [B,N,C]

    k1_prep<<<1 + DEG_BLOCKS + PREP_BLOCKS, 256>>>(x, weight, att, node_idx, hedge_idx);
    k2_scan_aedge<<<626, 1024>>>(node_idx);
    k3_scatter_stats<<<DEG_BLOCKS, 256>>>(node_idx, hedge_idx);
    k4_pass1m<<<HH, 128>>>(node_idx, weight);
    k5_pass2<<<(NN * 32 + 255) / 256, 256>>>(out);
}

// round 16
// speedup vs baseline: 1.0165x; 1.0165x over previous
#include <cuda_runtime.h>
#include <cuda_fp16.h>

// Problem constants (fixed by the dataset)
#define NN 50000      // nodes
#define HH 5000       // hyperedges
#define EE 400000     // incidence entries
#define RR (NN*2)     // (n,b) rows, r = 2n+b

#define DEG_BLOCKS 1563   // ceil(EE/256)
#define PREP_BLOCKS 12500 // RR/8 rows, 8 warps per block
#define SCHUNK 49         // scan chunk: 1024*49 >= NN

// ---------------------------------------------------------------------------
// Scratch (__device__ globals; zero-initialized at load; self-resetting)
// ---------------------------------------------------------------------------
__device__ __align__(16) __half g_xh[RR * 64];   // fp16 x, row r=2n+b (12.8 MB)
__device__ __align__(16) float  g_d1[RR];        // x . (W@att1)
__device__ __align__(16) float  g_d2[RR];        // x . (W@att2)
__device__ __align__(16) float  g_w[128];        // w1[64], w2[64]
__device__ volatile int g_wflag;                 // w ready flag (never reset; benign)
__device__ int   g_Dn[NN];                       // node degree (reset in pass2)
__device__ int   g_nstart[NN];                   // node segment starts
__device__ int   g_cursor[NN];                   // scatter cursors (reset by last-arriver)
__device__ int   g_done[NN];                     // completion counts (reset by last-arriver)
__device__ int   g_hstart[HH + 1];               // hyperedge segment starts (+sentinel)
__device__ __align__(16) float  g_aedge[HH * 2]; // per-hyperedge attention scalar
__device__ int   g_sh[EE];                       // hyperedge id per node-sorted slot
__device__ __align__(16) float  g_ni[NN * 8];    // per-node {d1_0,d1_1,mx0,mx1,inv0,inv1,deg,-}
__device__ __align__(16) __half g_mh[HH * 128];  // projected messages m (fp16)

// ---------------------------------------------------------------------------
// K1: block 0        -> g_w = {W@att1, W@att2}, then release flag
//     blocks 1..1563 -> node degrees (atomic) + hstart boundary fill
//     blocks 1564..  -> per-row d1,d2 + fp16 quantize of x (spin on flag)
// ---------------------------------------------------------------------------
__global__ void k1_prep(const float* __restrict__ x,
                        const float* __restrict__ W,
                        const float* __restrict__ att,
                        const int* __restrict__ node_idx,
                        const int* __restrict__ hedge_idx) {
    int b = blockIdx.x, t = threadIdx.x;
    if (b == 0) {
        if (t < 128) {
            int d = t & 63;
            const float* a = att + (t >> 6) * 64;
            float s = 0.f;
#pragma unroll
            for (int c = 0; c < 64; c++) s += W[d * 64 + c] * a[c];  // row d of W
            g_w[t] = s;
        }
        __syncthreads();
        __threadfence();
        if (t == 0) g_wflag = 1;
    } else if (b <= DEG_BLOCKS) {
        int e = (b - 1) * 256 + t;
        if (e >= EE) return;
        atomicAdd(&g_Dn[node_idx[e]], 1);
        int h  = hedge_idx[e];
        int hp = (e == 0) ? -1 : hedge_idx[e - 1];
        if (h != hp)
            for (int g = hp + 1; g <= h; g++) g_hstart[g] = e;
        if (e == EE - 1)
            for (int g = h + 1; g <= HH; g++) g_hstart[g] = EE;
    } else {
        if (t == 0) { while (g_wflag == 0) __nanosleep(64); }
        __syncthreads();            // block-wide fence: g_w visible after flag
        int warp = t >> 5, lane = t & 31;
        int r = (b - (DEG_BLOCKS + 1)) * 8 + warp;   // < RR always
        int n = r >> 1, bb = r & 1;
        float2 xv = *(const float2*)(x + (size_t)bb * NN * 64 + (size_t)n * 64 + lane * 2);
        float2 w1 = *(const float2*)(g_w + 2 * lane);
        float2 w2 = *(const float2*)(g_w + 64 + 2 * lane);
        float p1 = xv.x * w1.x + xv.y * w1.y;
        float p2 = xv.x * w2.x + xv.y * w2.y;
#pragma unroll
        for (int off = 16; off >= 1; off >>= 1) {
            p1 += __shfl_xor_sync(0xffffffffu, p1, off);
            p2 += __shfl_xor_sync(0xffffffffu, p2, off);
        }
        if (lane == 0) { g_d1[r] = p1; g_d2[r] = p2; }
        *(__half2*)(g_xh + (size_t)r * 64 + lane * 2) = __floats2half2_rn(xv.x, xv.y);
    }
}

// ---------------------------------------------------------------------------
// K2: block 0 (1024 thr) = exclusive scan of Dn -> nstart (49 elems/thread)
//     blocks 1..625      = 8 hyperedges each: aedge[h][b] = sum d2[2n+b]
// ---------------------------------------------------------------------------
__global__ void k2_scan_aedge(const int* __restrict__ node_idx) {
    int t = threadIdx.x;
    if (blockIdx.x == 0) {
        int begin = t * SCHUNK;
        int end   = min(begin + SCHUNK, NN);
        int s = 0;
        for (int i = begin; i < end; i++) s += g_Dn[i];
        int lane = t & 31, wid = t >> 5;
        int inc = s;
#pragma unroll
        for (int off = 1; off < 32; off <<= 1) {
            int y = __shfl_up_sync(0xffffffffu, inc, off);
            if (lane >= off) inc += y;
        }
        __shared__ int ws[32];
        if (lane == 31) ws[wid] = inc;
        __syncthreads();
        if (wid == 0) {
            int v = ws[lane];
#pragma unroll
            for (int off = 1; off < 32; off <<= 1) {
                int y = __shfl_up_sync(0xffffffffu, v, off);
                if (lane >= off) v += y;
            }
            ws[lane] = v;
        }
        __syncthreads();
        int run = inc - s + ((wid > 0) ? ws[wid - 1] : 0);
        for (int i = begin; i < end; i++) { g_nstart[i] = run; run += g_Dn[i]; }
    } else {
        int g  = t >> 7;            // group 0..7, 128 threads each
        int gt = t & 127;
        int h  = (blockIdx.x - 1) * 8 + g;    // < 5000 exactly (625*8)
        int s  = g_hstart[h];
        int cnt = g_hstart[h + 1] - s;
        float s0 = 0.f, s1 = 0.f;
        for (int i = gt; i < cnt; i += 128) {
            int n = node_idx[s + i];
            float2 d = *(const float2*)(g_d2 + 2 * n);
            s0 += d.x; s1 += d.y;
        }
#pragma unroll
        for (int off = 16; off >= 1; off >>= 1) {
            s0 += __shfl_xor_sync(0xffffffffu, s0, off);
            s1 += __shfl_xor_sync(0xffffffffu, s1, off);
        }
        __shared__ float r0[8][4], r1[8][4];
        int lane = gt & 31, wig = gt >> 5;
        if (lane == 0) { r0[g][wig] = s0; r1[g][wig] = s1; }
        __syncthreads();
        if (gt == 0) {
            g_aedge[2 * h]     = r0[g][0] + r0[g][1] + r0[g][2] + r0[g][3];
            g_aedge[2 * h + 1] = r1[g][0] + r1[g][1] + r1[g][2] + r1[g][3];
        }
    }
}

// ---------------------------------------------------------------------------
// K3: counting-sort scatter + last-arriver computes per-node softmax stats.
//     Release/acquire via the done-counter atomic itself; winner self-resets.
// ---------------------------------------------------------------------------
__global__ void k3_scatter_stats(const int* __restrict__ node_idx,
                                 const int* __restrict__ hedge_idx) {
    int e = blockIdx.x * 256 + threadIdx.x;
    if (e >= EE) return;
    int n = node_idx[e], h = hedge_idx[e];
    int pos = g_nstart[n] + atomicAdd(&g_cursor[n], 1);
    g_sh[pos] = h;
    int deg = g_Dn[n];
    int old;
    asm volatile("atom.acq_rel.gpu.global.add.s32 %0, [%1], %2;"
                 : "=r"(old) : "l"(g_done + n), "r"(1) : "memory");
    if (old == deg - 1) {
        g_cursor[n] = 0; g_done[n] = 0;       // self-reset (no more writers for n)
        int start = g_nstart[n];
        float d10 = g_d1[2 * n], d11 = g_d1[2 * n + 1];
        float m0 = -1e30f, m1 = -1e30f, s0 = 0.f, s1 = 0.f;
        for (int j = 0; j < deg; j++) {
            int hh = g_sh[start + j];
            float2 ae = *(const float2*)(g_aedge + 2 * hh);
            float v0 = d10 + ae.x; v0 = (v0 >= 0.f) ? v0 : 0.2f * v0;
            float v1 = d11 + ae.y; v1 = (v1 >= 0.f) ? v1 : 0.2f * v1;
            if (v0 > m0) { s0 = s0 * __expf(m0 - v0) + 1.f; m0 = v0; }
            else         { s0 += __expf(v0 - m0); }
            if (v1 > m1) { s1 = s1 * __expf(m1 - v1) + 1.f; m1 = v1; }
            else         { s1 += __expf(v1 - m1); }
        }
        *(float4*)(g_ni + n * 8)     = make_float4(d10, d11, m0, m1);
        *(float4*)(g_ni + n * 8 + 4) = make_float4(1.f / s0, 1.f / s1, (float)deg, 0.f);
    }
}

// fused-multiply-accumulate of one 16B half8 chunk into two float4 accs
#define FMA8(raw, a, alo, ahi) do {                                    \
    float2 _u0 = __half22float2(*(const __half2*)&(raw).x);            \
    float2 _u1 = __half22float2(*(const __half2*)&(raw).y);            \
    float2 _u2 = __half22float2(*(const __half2*)&(raw).z);            \
    float2 _u3 = __half22float2(*(const __half2*)&(raw).w);            \
    (alo).x += (a) * _u0.x; (alo).y += (a) * _u0.y;                    \
    (alo).z += (a) * _u1.x; (alo).w += (a) * _u1.y;                    \
    (ahi).x += (a) * _u2.x; (ahi).y += (a) * _u2.y;                    \
    (ahi).z += (a) * _u3.x; (ahi).w += (a) * _u3.y;                    \
} while (0)

// ---------------------------------------------------------------------------
// K4: pass1 + projection fused (block per hyperedge, 128 threads):
//     Half-warp owns 128B of the 256B node row (uint4/lane); warp covers 2
//     incidences per LDG.128. Inner loop software-pipelined 4 deep (MLP=4).
//     agg = (1/cnt) * sum alpha_e * x_fp16[n_e];  m = agg @ W -> g_mh (fp16)
// ---------------------------------------------------------------------------
__global__ void k4_pass1m(const int* __restrict__ node_idx,
                          const float* __restrict__ W) {
    int h = blockIdx.x, t = threadIdx.x;
    int s = g_hstart[h];
    int cnt = g_hstart[h + 1] - s;
    if (cnt == 0) { g_mh[h * 128 + t] = __float2half(0.f); return; }
    float2 ae = *(const float2*)(g_aedge + 2 * h);

    int w    = t >> 5;            // warp 0..3
    int lane = t & 31;
    int half = lane >> 4;         // which incidence of the warp's pair
    int hl   = lane & 15;         // owns halfs [hl*8, hl*8+8) of the row
    int bsel = hl >> 3;           // batch of those 8 halfs

    __shared__ int   sn[128];
    __shared__ float sa[2][128];
    __shared__ __align__(16) float red[4][32][8];
    __shared__ float sA[128];

    const __half* xrow = g_xh + hl * 8;
    float4 alo = make_float4(0.f, 0.f, 0.f, 0.f);
    float4 ahi = make_float4(0.f, 0.f, 0.f, 0.f);
    for (int base = 0; base < cnt; base += 128) {
        int mlen = min(128, cnt - base);
        __syncthreads();
        if (t < mlen) {
            int n = node_idx[s + base + t];
            float4 na = *(const float4*)(g_ni + n * 8);
            float4 nb = *(const float4*)(g_ni + n * 8 + 4);
            float v0 = na.x + ae.x; v0 = (v0 >= 0.f) ? v0 : 0.2f * v0;
            float v1 = na.y + ae.y; v1 = (v1 >= 0.f) ? v1 : 0.2f * v1;
            sn[t]    = n;
            sa[0][t] = __expf(v0 - na.z) * nb.x;
            sa[1][t] = __expf(v1 - na.w) * nb.y;
        }
        __syncthreads();
        int i = w * 2 + half;
        // 4 gathers in flight per warp-half
        for (; i + 24 < mlen; i += 32) {
            int n0 = sn[i], n1 = sn[i + 8], n2 = sn[i + 16], n3 = sn[i + 24];
            float a0 = sa[bsel][i],      a1 = sa[bsel][i + 8];
            float a2 = sa[bsel][i + 16], a3 = sa[bsel][i + 24];
            uint4 r0 = *(const uint4*)(xrow + (size_t)n0 * 128);
            uint4 r1 = *(const uint4*)(xrow + (size_t)n1 * 128);
            uint4 r2 = *(const uint4*)(xrow + (size_t)n2 * 128);
            uint4 r3 = *(const uint4*)(xrow + (size_t)n3 * 128);
            FMA8(r0, a0, alo, ahi);
            FMA8(r1, a1, alo, ahi);
            FMA8(r2, a2, alo, ahi);
            FMA8(r3, a3, alo, ahi);
        }
        for (; i < mlen; i += 8) {
            int n = sn[i];
            float a = sa[bsel][i];
            uint4 r = *(const uint4*)(xrow + (size_t)n * 128);
            FMA8(r, a, alo, ahi);
        }
    }
    *(float4*)&red[w][lane][0] = alo;
    *(float4*)&red[w][lane][4] = ahi;
    __syncthreads();
    // channel t: sum 8 partials (4 warps x 2 halves) for chunk t>>3, off t&7
    {
        int chunk = t >> 3, off = t & 7;
        float ssum = 0.f;
#pragma unroll
        for (int ww = 0; ww < 4; ww++)
            ssum += red[ww][chunk][off] + red[ww][16 + chunk][off];
        sA[t] = ssum * (1.0f / (float)cnt);
    }
    __syncthreads();
    // projection: thread t = (b, d); m[b][d] = sum_c agg[b][c] * W[c][d]
    int d = t & 63;
    const float* arow = sA + (t >> 6) * 64;
    float m = 0.f;
#pragma unroll 8
    for (int c = 0; c < 64; c++)
        m += arow[c] * __ldg(W + c * 64 + d);
    g_mh[h * 128 + t] = __float2half(m);
}

// ---------------------------------------------------------------------------
// K5: pass2: out[b][n][c] = deg * sum alpha_e * m_fp16[h_e] (warp per node)
//     Half-warp per incidence, uint4 loads, quad-batched gathers (MLP=4);
//     cross-half shfl_xor(16) reduction; resets g_Dn.
// ---------------------------------------------------------------------------
__global__ void k5_pass2(float* __restrict__ out) {
    int wip  = threadIdx.x >> 5;                       // warp in block (0..7)
    int gw   = (blockIdx.x * blockDim.x + threadIdx.x) >> 5;
    int lane = threadIdx.x & 31;
    __shared__ int    sh_h[8][32];
    __shared__ float2 sh_a[8][32];
    if (gw >= NN) return;
    int n = gw, deg = g_Dn[n];
    int start = g_nstart[n];
    float4 na = *(const float4*)(g_ni + n * 8);
    float4 nb = *(const float4*)(g_ni + n * 8 + 4);
    int half = lane >> 4;         // which incidence of the pair
    int hl   = lane & 15;         // owns halfs [hl*8, hl*8+8)
    int bsel = hl >> 3;           // batch of those 8 halfs
    const __half* mrow = g_mh + hl * 8;
    float4 alo = make_float4(0.f, 0.f, 0.f, 0.f);
    float4 ahi = make_float4(0.f, 0.f, 0.f, 0.f);

    for (int base = 0; base < deg; base += 32) {
        int cnt = min(32, deg - base);
        if (lane < cnt) {
            int h = g_sh[start + base + lane];
            float2 aev = *(const float2*)(g_aedge + 2 * h);
            float v0 = na.x + aev.x; v0 = (v0 >= 0.f) ? v0 : 0.2f * v0;
            float v1 = na.y + aev.y; v1 = (v1 >= 0.f) ? v1 : 0.2f * v1;
            sh_h[wip][lane] = h;
            sh_a[wip][lane] = make_float2(__expf(v0 - na.z) * nb.x,
                                          __expf(v1 - na.w) * nb.y);
        }
        __syncwarp();
        int i = half;
        for (; i + 6 < cnt; i += 8) {       // 4 gathers in flight
            int h0 = sh_h[wip][i],     h1 = sh_h[wip][i + 2];
            int h2 = sh_h[wip][i + 4], h3 = sh_h[wip][i + 6];
            float2 v0 = sh_a[wip][i],     v1 = sh_a[wip][i + 2];
            float2 v2 = sh_a[wip][i + 4], v3 = sh_a[wip][i + 6];
            float a0 = bsel ? v0.y : v0.x, a1 = bsel ? v1.y : v1.x;
            float a2 = bsel ? v2.y : v2.x, a3 = bsel ? v3.y : v3.x;
            uint4 r0 = *(const uint4*)(mrow + (size_t)h0 * 128);
            uint4 r1 = *(const uint4*)(mrow + (size_t)h1 * 128);
            uint4 r2 = *(const uint4*)(mrow + (size_t)h2 * 128);
            uint4 r3 = *(const uint4*)(mrow + (size_t)h3 * 128);
            FMA8(r0, a0, alo, ahi);
            FMA8(r1, a1, alo, ahi);
            FMA8(r2, a2, alo, ahi);
            FMA8(r3, a3, alo, ahi);
        }
        for (; i < cnt; i += 2) {
            int hh = sh_h[wip][i];
            float2 av = sh_a[wip][i];
            float aa = bsel ? av.y : av.x;
            uint4 r = *(const uint4*)(mrow + (size_t)hh * 128);
            FMA8(r, aa, alo, ahi);
        }
        __syncwarp();
    }
    // combine the two incidence-halves: lanes l and l+16 hold same channels
    alo.x += __shfl_xor_sync(0xffffffffu, alo.x, 16);
    alo.y += __shfl_xor_sync(0xffffffffu, alo.y, 16);
    alo.z += __shfl_xor_sync(0xffffffffu, alo.z, 16);
    alo.w += __shfl_xor_sync(0xffffffffu, alo.w, 16);
    ahi.x += __shfl_xor_sync(0xffffffffu, ahi.x, 16);
    ahi.y += __shfl_xor_sync(0xffffffffu, ahi.y, 16);
    ahi.z += __shfl_xor_sync(0xffffffffu, ahi.z, 16);
    ahi.w += __shfl_xor_sync(0xffffffffu, ahi.w, 16);
    if (lane == 0) g_Dn[n] = 0;       // self-reset for next replay
    if (half == 0) {
        float dn = (float)deg;
        int b  = hl >> 3;
        int c0 = (hl & 7) * 8;
        float* o = out + (size_t)b * NN * 64 + (size_t)n * 64 + c0;
        *(float4*)o       = make_float4(dn * alo.x, dn * alo.y, dn * alo.z, dn * alo.w);
        *(float4*)(o + 4) = make_float4(dn * ahi.x, dn * ahi.y, dn * ahi.z, dn * ahi.w);
    }
}

// ---------------------------------------------------------------------------
// Launch: 5 kernels
// ---------------------------------------------------------------------------
extern "C" void kernel_launch(void* const* d_in, const int* in_sizes, int n_in,
                              void* d_out, int out_size) {
    const float* x         = (const float*)d_in[0];   // [B,N,C]
    const float* weight    = (const float*)d_in[1];   // [C,C]
    const float* att       = (const float*)d_in[2];   // [2C]
    const int*   node_idx  = (const int*)d_in[3];     // [E]
    const int*   hedge_idx = (const int*)d_in[4];     // [E] sorted
    float*       out       = (float*)d_out;           // [B,N,C]

    k1_prep<<<1 + DEG_BLOCKS + PREP_BLOCKS, 256>>>(x, weight, att, node_idx, hedge_idx);
    k2_scan_aedge<<<626, 1024>>>(node_idx);
    k3_scatter_stats<<<DEG_BLOCKS, 256>>>(node_idx, hedge_idx);
    k4_pass1m<<<HH, 128>>>(node_idx, weight);
    k5_pass2<<<(NN * 32 + 255) / 256, 256>>>(out);
}